// round 11
// baseline (speedup 1.0000x reference)
#include <cuda_runtime.h>
#include <cstdint>

// Problem constants (fixed by the reference).
#define ROWS       8192
#define COLS       8192
#define NUMEL      (1ULL * ROWS * COLS)          // 64M output floats
#define NCODES     (NUMEL / 4)                   // 16M codes (centroid_len = 4)
#define CB_ENTRIES 512                           // 2 codebooks * 256 centroids (float4 each)

#define BLOCK      256
#define CPT        4                               // codes per thread per tile
#define TILE_CODES (BLOCK * CPT)                   // 1024 codes
#define TILE_BYTES (TILE_CODES * 16)               // 16 KB output per tile
#define NTILES     ((int)(NCODES / TILE_CODES))    // 16384 (exact)
#define DEPTH      3                               // smem output buffers
#define GRID       (152 * 4)                       // 608 blocks (4/SM: 56KB smem)

// Dequant, fully pipelined:
//  - codes/scales for tile i+1 prefetched into registers while tile i computes
//    (hides the code LDG round trip completely)
//  - output staged in 3 rotating 16KB smem buffers, streamed out with
//    cp.async.bulk (wait_group.read 2 -> up to 2 stores in flight)
// DRAM sees large sequential bursts on the write side and never stalls a warp.

__device__ __forceinline__ void load_tile(
    const int* __restrict__ codes, const float* __restrict__ scales,
    int tile, int t, int* c, float* s)
{
    const long long base = (long long)tile * TILE_CODES;
    const int*   cp = codes  + base;
    const float* sp = scales + (base >> 4);
    #pragma unroll
    for (int k = 0; k < CPT; k++)
        c[k] = __ldg(cp + k * BLOCK + t);
    #pragma unroll
    for (int k = 0; k < CPT; k++)
        s[k] = __ldg(sp + ((k * BLOCK + t) >> 4));
}

__device__ __forceinline__ void store_tile(
    const float4* __restrict__ s_cb, float4 (*s_out)[TILE_CODES],
    float4* __restrict__ out4,
    int iter, int tile, int t, const int* c, const float* s)
{
    const int buf = iter % DEPTH;
    const long long base = (long long)tile * TILE_CODES;
    const int cb_off = (tile >= (NTILES / 2)) ? 256 : 0;

    // Buffer reuse: allow up to DEPTH-1 bulk stores still reading smem.
    if (t == 0)
        asm volatile("cp.async.bulk.wait_group.read %0;" :: "n"(DEPTH - 1) : "memory");
    __syncthreads();

    #pragma unroll
    for (int k = 0; k < CPT; k++) {
        float4 v = s_cb[cb_off + c[k]];
        v.x *= s[k]; v.y *= s[k]; v.z *= s[k]; v.w *= s[k];
        s_out[buf][k * BLOCK + t] = v;
    }
    __syncthreads();

    if (t == 0) {
        asm volatile("fence.proxy.async.shared::cta;" ::: "memory");
        uint32_t src;
        asm("{ .reg .u64 a; cvta.to.shared.u64 a, %1; cvt.u32.u64 %0, a; }"
            : "=r"(src) : "l"(&s_out[buf][0]));
        asm volatile(
            "cp.async.bulk.global.shared::cta.bulk_group [%0], [%1], %2;"
            :: "l"(out4 + base), "r"(src), "n"(TILE_BYTES) : "memory");
        asm volatile("cp.async.bulk.commit_group;" ::: "memory");
    }
}

__global__ __launch_bounds__(BLOCK) void dequant_kernel(
    const float4* __restrict__ codebooks,   // [512] float4
    const float*  __restrict__ scales,      // [NUMEL/64]
    const int*    __restrict__ codes,       // [NCODES]
    float4*       __restrict__ out4)        // [NCODES]
{
    __shared__ float4 s_cb[CB_ENTRIES];                        // 8 KB
    __shared__ __align__(128) float4 s_out[DEPTH][TILE_CODES]; // 3 x 16 KB

    for (int i = threadIdx.x; i < CB_ENTRIES; i += BLOCK)
        s_cb[i] = codebooks[i];
    __syncthreads();

    const int t      = threadIdx.x;
    const int stride = gridDim.x;

    int tile = blockIdx.x;          // grid <= NTILES, so tile is valid
    int iter = 0;

    int   cA[CPT], cB[CPT];
    float sA[CPT], sB[CPT];

    load_tile(codes, scales, tile, t, cA, sA);

    while (true) {
        // --- consume A, prefetch next tile into B ---
        {
            int nxt = tile + stride;
            if (nxt < NTILES)
                load_tile(codes, scales, nxt, t, cB, sB);
            store_tile(s_cb, s_out, out4, iter, tile, t, cA, sA);
            tile = nxt; iter++;
            if (tile >= NTILES) break;
        }
        // --- consume B, prefetch next tile into A ---
        {
            int nxt = tile + stride;
            if (nxt < NTILES)
                load_tile(codes, scales, nxt, t, cA, sA);
            store_tile(s_cb, s_out, out4, iter, tile, t, cB, sB);
            tile = nxt; iter++;
            if (tile >= NTILES) break;
        }
    }

    // Drain all outstanding bulk stores before exit.
    if (t == 0)
        asm volatile("cp.async.bulk.wait_group 0;" ::: "memory");
}

extern "C" void kernel_launch(void* const* d_in, const int* in_sizes, int n_in,
                              void* d_out, int out_size)
{
    // metadata order: codebooks [2,256,4] f32, scales [1M,1] f32, codes [2,8M] i32, rows, columns
    const float4* codebooks = (const float4*)d_in[0];
    const float*  scales    = (const float*)d_in[1];
    const int*    codes     = (const int*)d_in[2];
    float4*       out4      = (float4*)d_out;

    int grid = GRID;
    if (grid > NTILES) grid = NTILES;

    dequant_kernel<<<grid, BLOCK>>>(codebooks, scales, codes, out4);
}